// round 6
// baseline (speedup 1.0000x reference)
#include <cuda_runtime.h>

#define TT 1024
#define BB 32
#define II 512
#define HH 512
#define GG 2048
#define NBLK 128
#define NTH 512
#define CK 128
#define NCHUNK 4
#define KPT 8
#define NSLICE 16
#define STRD 36

// shared memory layout (float offsets)
#define OFF_W    0        // 4 mats * 512 k * 16 rows (k-major, stride 16)   = 32768
#define OFF_STG  32768    // union: U(128*36)+V(128*36)=9216 | RED 512*17=8704
#define OFF_U    OFF_STG
#define OFF_V    (OFF_STG + 4608)
#define OFF_RED  OFF_STG
#define OFF_H0   41984    // 2 * 512
#define OFF_BIAS 43008    // 2 * 16
#define OFF_C    43040    // 2 * 4 * 32
#define OFF_C0   43296    // 2 * 4
#define OFF_M    43304    // 32 ints
#define SMEM_FLOATS 43336
#define SMEM_BYTES (SMEM_FLOATS * 4)

typedef unsigned long long u64;

__device__ __forceinline__ u64 pack2(float x, float y) {
    u64 r; asm("mov.b64 %0, {%1, %2};" : "=l"(r) : "f"(x), "f"(y)); return r;
}
__device__ __forceinline__ void ffma2(u64& d, u64 a, u64 b) {
    asm("fma.rn.f32x2 %0, %1, %2, %0;" : "+l"(d) : "l"(a), "l"(b));
}
__device__ __forceinline__ void unpack2(u64 p, float& x, float& y) {
    asm("mov.b64 {%0, %1}, %2;" : "=f"(x), "=f"(y) : "l"(p));
}

__device__ float g_h[2][2][BB][HH];   // [layer][parity][batch][unit]
__device__ unsigned g_cnt;
__device__ unsigned g_gen;

__device__ __forceinline__ void grid_sync() {
    __syncthreads();
    if (threadIdx.x == 0) {
        __threadfence();
        unsigned gen = *(volatile unsigned*)&g_gen;
        unsigned old = atomicAdd(&g_cnt, 1u);
        if (old == NBLK - 1) {
            *(volatile unsigned*)&g_cnt = 0u;
            __threadfence();
            atomicAdd(&g_gen, 1u);
        } else {
            while (*(volatile unsigned*)&g_gen == gen) { __nanosleep(20); }
        }
        __threadfence();
    }
    __syncthreads();
}

__device__ __forceinline__ float sigf(float x) {
    return 1.0f / (1.0f + __expf(-x));
}

// One layer-phase: gates = U @ WmatA^T + V_masked @ WmatB^T + bias; LSTM cell update.
__device__ __forceinline__ void phase(
    float* __restrict__ sm,
    const int* __restrict__ mS,
    const float* __restrict__ h0l,
    const float* __restrict__ Ug,           // [32][512] global, unmasked
    const float* __restrict__ Vg,           // [32][512] global, masked by mS
    int matA, int matB, int l,
    float* __restrict__ hOut,
    float* __restrict__ outT,
    float* __restrict__ hN, float* __restrict__ cN, bool last,
    int j0, int tid, int bq, int rq, int ks)
{
    float* wS   = sm + OFF_W;
    float* uS   = sm + OFF_U;
    float* vS   = sm + OFF_V;
    float* redS = sm + OFF_RED;
    float* cS   = sm + OFF_C;
    float* c0S  = sm + OFF_C0;
    float* biasS= sm + OFF_BIAS;

    u64 acc[8];   // [i=0..3][jp=0..1]: lanes (bq*4+2jp, bq*4+2jp+1)
#pragma unroll
    for (int i = 0; i < 8; i++) acc[i] = 0ull;

    // staging coords: lane = batch, warp owns k-quads {w0, w0+16}
    const int sb = tid & 31;
    const int w0 = tid >> 5;                // 0..15

    float4 ru[2], rv[2];
    const int msb = mS[sb];
    // prefetch chunk 0
#pragma unroll
    for (int e = 0; e < 2; e++) {
        int kg = (w0 + 16 * e) * 4;
        float4 uval = __ldcg((const float4*)(Ug + sb * 512 + kg));
        float4 hv   = __ldcg((const float4*)(Vg + sb * 512 + kg));
        ru[e] = uval;
        rv[e] = msb ? *(const float4*)(h0l + kg) : hv;
    }

    for (int c = 0; c < NCHUNK; c++) {
        __syncthreads();   // previous consumers of uS/vS done
        // store prefetched chunk: transpose scatter, conflict-free (bank = lane)
#pragma unroll
        for (int e = 0; e < 2; e++) {
            int kq = (w0 + 16 * e) * 4;
            uS[(kq + 0) * STRD + sb] = ru[e].x;
            uS[(kq + 1) * STRD + sb] = ru[e].y;
            uS[(kq + 2) * STRD + sb] = ru[e].z;
            uS[(kq + 3) * STRD + sb] = ru[e].w;
            vS[(kq + 0) * STRD + sb] = rv[e].x;
            vS[(kq + 1) * STRD + sb] = rv[e].y;
            vS[(kq + 2) * STRD + sb] = rv[e].z;
            vS[(kq + 3) * STRD + sb] = rv[e].w;
        }
        // prefetch next chunk (overlaps with compute of this chunk)
        if (c < NCHUNK - 1) {
#pragma unroll
            for (int e = 0; e < 2; e++) {
                int kg = (c + 1) * CK + (w0 + 16 * e) * 4;
                float4 uval = __ldcg((const float4*)(Ug + sb * 512 + kg));
                float4 hv   = __ldcg((const float4*)(Vg + sb * 512 + kg));
                ru[e] = uval;
                rv[e] = msb ? *(const float4*)(h0l + kg) : hv;
            }
        }
        __syncthreads();

        int kc0 = c * CK;
        int kbase = ks * KPT;
        const float* wA = wS + (matA * 512 + kc0) * 16;
        const float* wB = wS + (matB * 512 + kc0) * 16;
#pragma unroll
        for (int kk = 0; kk < KPT; kk++) {
            int k = kbase + kk;
            float4 uq  = *(const float4*)(uS + k * STRD + bq * 4);
            float4 vq  = *(const float4*)(vS + k * STRD + bq * 4);
            float4 wa4 = *(const float4*)(wA + k * 16 + rq * 4);
            float4 wb4 = *(const float4*)(wB + k * 16 + rq * 4);
            u64 u01 = pack2(uq.x, uq.y), u23 = pack2(uq.z, uq.w);
            u64 v01 = pack2(vq.x, vq.y), v23 = pack2(vq.z, vq.w);
            {
                u64 d0 = pack2(wa4.x, wa4.x); ffma2(acc[0], d0, u01); ffma2(acc[1], d0, u23);
                u64 d1 = pack2(wa4.y, wa4.y); ffma2(acc[2], d1, u01); ffma2(acc[3], d1, u23);
                u64 d2 = pack2(wa4.z, wa4.z); ffma2(acc[4], d2, u01); ffma2(acc[5], d2, u23);
                u64 d3 = pack2(wa4.w, wa4.w); ffma2(acc[6], d3, u01); ffma2(acc[7], d3, u23);
            }
            {
                u64 d0 = pack2(wb4.x, wb4.x); ffma2(acc[0], d0, v01); ffma2(acc[1], d0, v23);
                u64 d1 = pack2(wb4.y, wb4.y); ffma2(acc[2], d1, v01); ffma2(acc[3], d1, v23);
                u64 d2 = pack2(wb4.z, wb4.z); ffma2(acc[4], d2, v01); ffma2(acc[5], d2, v23);
                u64 d3 = pack2(wb4.w, wb4.w); ffma2(acc[6], d3, v01); ffma2(acc[7], d3, v23);
            }
        }
    }

    // ---- cross-k-slice reduction + LSTM cell update ----
    __syncthreads();   // all compute reads of uS/vS done (redS aliases them)
#pragma unroll
    for (int i = 0; i < 4; i++) {
#pragma unroll
        for (int jp = 0; jp < 2; jp++) {
            float fx, fy;
            unpack2(acc[i * 2 + jp], fx, fy);
            redS[(((rq * 4 + i) * 32) + bq * 4 + 2 * jp + 0) * 17 + ks] = fx;
            redS[(((rq * 4 + i) * 32) + bq * 4 + 2 * jp + 1) * 17 + ks] = fy;
        }
    }
    __syncthreads();

    if (tid < 128) {
        int u = tid >> 5;
        int b = tid & 31;
        float pre[4];
#pragma unroll
        for (int g = 0; g < 4; g++) {
            float s = biasS[l * 16 + g * 4 + u];
#pragma unroll
            for (int q = 0; q < NSLICE; q++)
                s += redS[((g * 4 + u) * 32 + b) * 17 + q];
            pre[g] = s;
        }
        float cp = cS[(l * 4 + u) * 32 + b];
        if (mS[b]) cp = c0S[l * 4 + u];
        float ig = sigf(pre[0]);
        float fg = sigf(pre[1]);
        float gg = tanhf(pre[2]);
        float og = sigf(pre[3]);
        float cn = fg * cp + ig * gg;
        float hn = og * tanhf(cn);
        cS[(l * 4 + u) * 32 + b] = cn;
        __stcg(hOut + b * HH + j0 + u, hn);
        if (outT) outT[b * HH + j0 + u] = hn;
        if (last) {
            hN[(l * BB + b) * HH + j0 + u] = hn;
            cN[(l * BB + b) * HH + j0 + u] = cn;
        }
    }
}

__global__ void __launch_bounds__(NTH, 1)
lstm_kernel(const float* __restrict__ x,
            const int* __restrict__ rmask,
            const float* __restrict__ w_ih,
            const float* __restrict__ w_hh,
            const float* __restrict__ b_ih,
            const float* __restrict__ b_hh,
            const float* __restrict__ h0,
            const float* __restrict__ c0,
            float* __restrict__ out)
{
    extern __shared__ float sm[];
    float* wS    = sm + OFF_W;
    float* h0S   = sm + OFF_H0;
    float* biasS = sm + OFF_BIAS;
    float* cS    = sm + OFF_C;
    float* c0S   = sm + OFF_C0;
    int*   mS    = (int*)(sm + OFF_M);

    const int tid = threadIdx.x;
    const int bid = blockIdx.x;
    const int j0 = bid * 4;

    const int bq = tid & 7;          // batch quad
    const int rq = (tid >> 3) & 3;   // row quad (gate)
    const int ks = tid >> 5;         // k slice (warp id), 0..15

    // ---- one-time weight load: k-major, 16 rows per matrix ----
    for (int f = tid; f < 4 * 16 * 512; f += NTH) {
        int k = f & 511;
        int mr = f >> 9;
        int m = mr >> 4;
        int r = mr & 15;
        int gate = r >> 2, u = r & 3;
        int row = gate * HH + j0 + u;
        int l = m >> 1;
        const float* src;
        if ((m & 1) == 0) src = w_ih + ((size_t)l * GG + row) * II + k;
        else              src = w_hh + ((size_t)l * GG + row) * HH + k;
        wS[(m * 512 + k) * 16 + r] = __ldg(src);
    }
    if (tid < 32) {
        int l = tid >> 4;
        int r = tid & 15;
        int gate = r >> 2, u = r & 3;
        int row = gate * HH + j0 + u;
        biasS[tid] = __ldg(b_ih + l * GG + row) + __ldg(b_hh + l * GG + row);
    }
    for (int f = tid; f < 2 * HH; f += NTH) h0S[f] = __ldg(h0 + f);
    if (tid < 8) {
        int l = tid >> 2, u = tid & 3;
        c0S[tid] = __ldg(c0 + l * HH + j0 + u);
    }
    __syncthreads();
    for (int f = tid; f < 2 * 4 * 32; f += NTH) {
        int l = f >> 7;
        int u = (f >> 5) & 3;
        cS[f] = c0S[l * 4 + u];
    }
    if (tid < 256) {
        int l = tid >> 7, b = (tid >> 2) & 31, u = tid & 3;
        __stcg(&g_h[l][0][b][j0 + u], h0S[l * HH + j0 + u]);
    }
    grid_sync();

    float* hN = out + (size_t)TT * BB * HH;
    float* cN = hN + 2 * BB * HH;

    for (int t = 0; t < TT; t++) {
        int par = t & 1;
        __syncthreads();  // prior epilogue readers of mS done
        if (tid < 32) mS[tid] = __ldg(rmask + t * BB + tid);
        __syncthreads();  // mS visible before phase1 prefetch
        bool last = (t == TT - 1);

        // phase 1: layer 0. U = x[t], V = masked h_l0(prev)
        phase(sm, mS, h0S,
              x + (size_t)t * BB * II,
              &g_h[0][par][0][0],
              0, 1, 0,
              &g_h[0][par ^ 1][0][0],
              nullptr, hN, cN, last,
              j0, tid, bq, rq, ks);

        grid_sync();

        // phase 2: layer 1. U = fresh h_l0, V = masked h_l1(prev)
        phase(sm, mS, h0S + HH,
              &g_h[0][par ^ 1][0][0],
              &g_h[1][par][0][0],
              2, 3, 1,
              &g_h[1][par ^ 1][0][0],
              out + (size_t)t * BB * HH, hN, cN, last,
              j0, tid, bq, rq, ks);
        // (no end-of-step grid sync needed: parity double-buffering makes the
        //  only cross-block hazards pass through the mid-step sync)
    }
}

extern "C" void kernel_launch(void* const* d_in, const int* in_sizes, int n_in,
                              void* d_out, int out_size) {
    const float* x    = (const float*)d_in[0];
    const int*   rm   = (const int*)d_in[1];
    const float* w_ih = (const float*)d_in[2];
    const float* w_hh = (const float*)d_in[3];
    const float* b_ih = (const float*)d_in[4];
    const float* b_hh = (const float*)d_in[5];
    const float* h0   = (const float*)d_in[6];
    const float* c0   = (const float*)d_in[7];
    float* out = (float*)d_out;

    cudaFuncSetAttribute(lstm_kernel, cudaFuncAttributeMaxDynamicSharedMemorySize, SMEM_BYTES);
    lstm_kernel<<<NBLK, NTH, SMEM_BYTES>>>(x, rm, w_ih, w_hh, b_ih, b_hh, h0, c0, out);
}

// round 9
// speedup vs baseline: 1.2887x; 1.2887x over previous
#include <cuda_runtime.h>

#define TT 1024
#define BB 32
#define II 512
#define HH 512
#define GG 2048
#define NBLK 128
#define NTH 512
#define CK 128
#define NCHUNK 4
#define KPT 8
#define NSLICE 16
#define STRD 36

// shared memory layout (float offsets)
#define OFF_W    0        // 4 mats * 512 k * 16 rows (k-major, stride 16)   = 32768
#define OFF_STG  32768    // union: U(128*36)+V(128*36)=9216 | RED 512*17=8704
#define OFF_U    OFF_STG
#define OFF_V    (OFF_STG + 4608)
#define OFF_RED  OFF_STG
#define OFF_H0   41984    // 2 * 512
#define OFF_BIAS 43008    // 2 * 16
#define OFF_C    43040    // 2 * 4 * 32
#define OFF_C0   43296    // 2 * 4
#define OFF_M    43304    // 32 ints
#define SMEM_FLOATS 43336
#define SMEM_BYTES (SMEM_FLOATS * 4)

typedef unsigned long long u64;

__device__ __forceinline__ u64 pack2(float x, float y) {
    u64 r; asm("mov.b64 %0, {%1, %2};" : "=l"(r) : "f"(x), "f"(y)); return r;
}
__device__ __forceinline__ void ffma2(u64& d, u64 a, u64 b) {
    asm("fma.rn.f32x2 %0, %1, %2, %0;" : "+l"(d) : "l"(a), "l"(b));
}
__device__ __forceinline__ void unpack2(u64 p, float& x, float& y) {
    asm("mov.b64 {%0, %1}, %2;" : "=f"(x), "=f"(y) : "l"(p));
}

__device__ float g_h[2][2][BB][HH];   // [layer][parity][batch][unit]
__device__ unsigned g_cnt;
__device__ unsigned g_gen;

__device__ __forceinline__ void grid_sync() {
    __syncthreads();
    if (threadIdx.x == 0) {
        __threadfence();
        unsigned gen = *(volatile unsigned*)&g_gen;
        unsigned old = atomicAdd(&g_cnt, 1u);
        if (old == NBLK - 1) {
            *(volatile unsigned*)&g_cnt = 0u;
            __threadfence();
            atomicAdd(&g_gen, 1u);
        } else {
            while (*(volatile unsigned*)&g_gen == gen) { __nanosleep(20); }
        }
        __threadfence();
    }
    __syncthreads();
}

__device__ __forceinline__ float sigf(float x) {
    return 1.0f / (1.0f + __expf(-x));
}

// One layer-phase: gates = U @ WmatA^T + V_masked @ WmatB^T + bias; LSTM cell update.
__device__ __forceinline__ void phase(
    float* __restrict__ sm,
    const int* __restrict__ mS,
    const float* __restrict__ h0l,
    const float* __restrict__ Ug,           // [32][512] global, unmasked
    const float* __restrict__ Vg,           // [32][512] global, masked by mS
    int matA, int matB, int l,
    float* __restrict__ hOut,
    float* __restrict__ outT,
    float* __restrict__ hN, float* __restrict__ cN, bool last,
    int j0, int tid, int bq, int rq, int ks)
{
    float* wS   = sm + OFF_W;
    float* uS   = sm + OFF_U;
    float* vS   = sm + OFF_V;
    float* redS = sm + OFF_RED;
    float* cS   = sm + OFF_C;
    float* c0S  = sm + OFF_C0;
    float* biasS= sm + OFF_BIAS;

    u64 acc[8];   // [i=0..3][jp=0..1]: lanes (bq*4+2jp, bq*4+2jp+1)
#pragma unroll
    for (int i = 0; i < 8; i++) acc[i] = 0ull;

    // staging coords: element (k = w*8 + kk, b = 4i + bh)
    //  LDG: per i, 4 rows x 32B consecutive -> 4 full sectors (coalesced)
    //  STS: bank = (4*kk + bh + 4i) mod 32 -> conflict-free
    const int kk = tid & 7;
    const int bh = (tid >> 3) & 3;
    const int kstg = (tid >> 5) * 8 + kk;   // 0..127

    float ru[8], rv[8];
    // prefetch chunk 0
    {
        float h0v = h0l[kstg];
#pragma unroll
        for (int i = 0; i < 8; i++) {
            int b = i * 4 + bh;
            float uval = __ldcg(Ug + b * 512 + kstg);
            float hv   = __ldcg(Vg + b * 512 + kstg);
            ru[i] = uval;
            rv[i] = mS[b] ? h0v : hv;
        }
    }

    for (int c = 0; c < NCHUNK; c++) {
        __syncthreads();   // previous consumers of uS/vS done
        // store prefetched chunk: conflict-free transpose scatter
#pragma unroll
        for (int i = 0; i < 8; i++) {
            int b = i * 4 + bh;
            uS[kstg * STRD + b] = ru[i];
            vS[kstg * STRD + b] = rv[i];
        }
        // prefetch next chunk (overlaps with compute of this chunk)
        if (c < NCHUNK - 1) {
            int kg = (c + 1) * CK + kstg;
            float h0v = h0l[kg];
#pragma unroll
            for (int i = 0; i < 8; i++) {
                int b = i * 4 + bh;
                float uval = __ldcg(Ug + b * 512 + kg);
                float hv   = __ldcg(Vg + b * 512 + kg);
                ru[i] = uval;
                rv[i] = mS[b] ? h0v : hv;
            }
        }
        __syncthreads();

        int kc0 = c * CK;
        int kbase = ks * KPT;
        const float* wA = wS + (matA * 512 + kc0) * 16;
        const float* wB = wS + (matB * 512 + kc0) * 16;
#pragma unroll
        for (int kkk = 0; kkk < KPT; kkk++) {
            int k = kbase + kkk;
            float4 uq  = *(const float4*)(uS + k * STRD + bq * 4);
            float4 vq  = *(const float4*)(vS + k * STRD + bq * 4);
            float4 wa4 = *(const float4*)(wA + k * 16 + rq * 4);
            float4 wb4 = *(const float4*)(wB + k * 16 + rq * 4);
            u64 u01 = pack2(uq.x, uq.y), u23 = pack2(uq.z, uq.w);
            u64 v01 = pack2(vq.x, vq.y), v23 = pack2(vq.z, vq.w);
            {
                u64 d0 = pack2(wa4.x, wa4.x); ffma2(acc[0], d0, u01); ffma2(acc[1], d0, u23);
                u64 d1 = pack2(wa4.y, wa4.y); ffma2(acc[2], d1, u01); ffma2(acc[3], d1, u23);
                u64 d2 = pack2(wa4.z, wa4.z); ffma2(acc[4], d2, u01); ffma2(acc[5], d2, u23);
                u64 d3 = pack2(wa4.w, wa4.w); ffma2(acc[6], d3, u01); ffma2(acc[7], d3, u23);
            }
            {
                u64 d0 = pack2(wb4.x, wb4.x); ffma2(acc[0], d0, v01); ffma2(acc[1], d0, v23);
                u64 d1 = pack2(wb4.y, wb4.y); ffma2(acc[2], d1, v01); ffma2(acc[3], d1, v23);
                u64 d2 = pack2(wb4.z, wb4.z); ffma2(acc[4], d2, v01); ffma2(acc[5], d2, v23);
                u64 d3 = pack2(wb4.w, wb4.w); ffma2(acc[6], d3, v01); ffma2(acc[7], d3, v23);
            }
        }
    }

    // ---- cross-k-slice reduction + LSTM cell update ----
    __syncthreads();   // all compute reads of uS/vS done (redS aliases them)
#pragma unroll
    for (int i = 0; i < 4; i++) {
#pragma unroll
        for (int jp = 0; jp < 2; jp++) {
            float fx, fy;
            unpack2(acc[i * 2 + jp], fx, fy);
            redS[(((rq * 4 + i) * 32) + bq * 4 + 2 * jp + 0) * 17 + ks] = fx;
            redS[(((rq * 4 + i) * 32) + bq * 4 + 2 * jp + 1) * 17 + ks] = fy;
        }
    }
    __syncthreads();

    if (tid < 128) {
        int u = tid >> 5;
        int b = tid & 31;
        float pre[4];
#pragma unroll
        for (int g = 0; g < 4; g++) {
            float s = biasS[l * 16 + g * 4 + u];
#pragma unroll
            for (int q = 0; q < NSLICE; q++)
                s += redS[((g * 4 + u) * 32 + b) * 17 + q];
            pre[g] = s;
        }
        float cp = cS[(l * 4 + u) * 32 + b];
        if (mS[b]) cp = c0S[l * 4 + u];
        float ig = sigf(pre[0]);
        float fg = sigf(pre[1]);
        float gg = tanhf(pre[2]);
        float og = sigf(pre[3]);
        float cn = fg * cp + ig * gg;
        float hn = og * tanhf(cn);
        cS[(l * 4 + u) * 32 + b] = cn;
        __stcg(hOut + b * HH + j0 + u, hn);
        if (outT) outT[b * HH + j0 + u] = hn;
        if (last) {
            hN[(l * BB + b) * HH + j0 + u] = hn;
            cN[(l * BB + b) * HH + j0 + u] = cn;
        }
    }
}

__global__ void __launch_bounds__(NTH, 1)
lstm_kernel(const float* __restrict__ x,
            const int* __restrict__ rmask,
            const float* __restrict__ w_ih,
            const float* __restrict__ w_hh,
            const float* __restrict__ b_ih,
            const float* __restrict__ b_hh,
            const float* __restrict__ h0,
            const float* __restrict__ c0,
            float* __restrict__ out)
{
    extern __shared__ float sm[];
    float* wS    = sm + OFF_W;
    float* h0S   = sm + OFF_H0;
    float* biasS = sm + OFF_BIAS;
    float* cS    = sm + OFF_C;
    float* c0S   = sm + OFF_C0;
    int*   mS    = (int*)(sm + OFF_M);

    const int tid = threadIdx.x;
    const int bid = blockIdx.x;
    const int j0 = bid * 4;

    const int bq = tid & 7;          // batch quad
    const int rq = (tid >> 3) & 3;   // row quad (gate)
    const int ks = tid >> 5;         // k slice (warp id), 0..15

    // ---- one-time weight load: k-major, 16 rows per matrix ----
    for (int f = tid; f < 4 * 16 * 512; f += NTH) {
        int k = f & 511;
        int mr = f >> 9;
        int m = mr >> 4;
        int r = mr & 15;
        int gate = r >> 2, u = r & 3;
        int row = gate * HH + j0 + u;
        int l = m >> 1;
        const float* src;
        if ((m & 1) == 0) src = w_ih + ((size_t)l * GG + row) * II + k;
        else              src = w_hh + ((size_t)l * GG + row) * HH + k;
        wS[(m * 512 + k) * 16 + r] = __ldg(src);
    }
    if (tid < 32) {
        int l = tid >> 4;
        int r = tid & 15;
        int gate = r >> 2, u = r & 3;
        int row = gate * HH + j0 + u;
        biasS[tid] = __ldg(b_ih + l * GG + row) + __ldg(b_hh + l * GG + row);
    }
    for (int f = tid; f < 2 * HH; f += NTH) h0S[f] = __ldg(h0 + f);
    if (tid < 8) {
        int l = tid >> 2, u = tid & 3;
        c0S[tid] = __ldg(c0 + l * HH + j0 + u);
    }
    __syncthreads();
    for (int f = tid; f < 2 * 4 * 32; f += NTH) {
        int l = f >> 7;
        int u = (f >> 5) & 3;
        cS[f] = c0S[l * 4 + u];
    }
    if (tid < 256) {
        int l = tid >> 7, b = (tid >> 2) & 31, u = tid & 3;
        __stcg(&g_h[l][0][b][j0 + u], h0S[l * HH + j0 + u]);
    }
    grid_sync();

    float* hN = out + (size_t)TT * BB * HH;
    float* cN = hN + 2 * BB * HH;

    for (int t = 0; t < TT; t++) {
        int par = t & 1;
        __syncthreads();  // prior epilogue readers of mS done
        if (tid < 32) mS[tid] = __ldg(rmask + t * BB + tid);
        __syncthreads();  // mS visible before phase1 prefetch
        bool last = (t == TT - 1);

        // phase 1: layer 0. U = x[t], V = masked h_l0(prev)
        phase(sm, mS, h0S,
              x + (size_t)t * BB * II,
              &g_h[0][par][0][0],
              0, 1, 0,
              &g_h[0][par ^ 1][0][0],
              nullptr, hN, cN, last,
              j0, tid, bq, rq, ks);

        grid_sync();

        // phase 2: layer 1. U = fresh h_l0, V = masked h_l1(prev)
        phase(sm, mS, h0S + HH,
              &g_h[0][par ^ 1][0][0],
              &g_h[1][par][0][0],
              2, 3, 1,
              &g_h[1][par ^ 1][0][0],
              out + (size_t)t * BB * HH, hN, cN, last,
              j0, tid, bq, rq, ks);
        // (no end-of-step grid sync needed: parity double-buffering makes the
        //  only cross-block hazards pass through the mid-step sync)
    }
}

extern "C" void kernel_launch(void* const* d_in, const int* in_sizes, int n_in,
                              void* d_out, int out_size) {
    const float* x    = (const float*)d_in[0];
    const int*   rm   = (const int*)d_in[1];
    const float* w_ih = (const float*)d_in[2];
    const float* w_hh = (const float*)d_in[3];
    const float* b_ih = (const float*)d_in[4];
    const float* b_hh = (const float*)d_in[5];
    const float* h0   = (const float*)d_in[6];
    const float* c0   = (const float*)d_in[7];
    float* out = (float*)d_out;

    cudaFuncSetAttribute(lstm_kernel, cudaFuncAttributeMaxDynamicSharedMemorySize, SMEM_BYTES);
    lstm_kernel<<<NBLK, NTH, SMEM_BYTES>>>(x, rm, w_ih, w_hh, b_ih, b_hh, h0, c0, out);
}

// round 10
// speedup vs baseline: 1.5385x; 1.1938x over previous
#include <cuda_runtime.h>

#define TT 1024
#define BB 32
#define II 512
#define HH 512
#define GG 2048
#define NBLK 128
#define NTH 512
#define CK 128
#define NCHUNK 4
#define KPT 8
#define NSLICE 16

// shared memory layout (float offsets)
#define OFF_W    0        // 4 mats * 512 k * 16 rows (k-major, stride 16) = 32768
#define OFF_STG  32768    // two staging buffers of 8448 (U 4224 + V 4224)
#define BUFSZ    8448
#define OFF_RED  32768    // 512*17 = 8704, aliases buf0 + head of buf1 (dead at red time)
#define OFF_H0   49664    // 2 * 512
#define OFF_BIAS 50688    // 2 * 16
#define OFF_C    50720    // 2 * 4 * 32
#define OFF_C0   50976    // 2 * 4
#define OFF_M    50984    // 32 ints
#define SMEM_FLOATS 51016
#define SMEM_BYTES (SMEM_FLOATS * 4)

__device__ float g_h[2][2][BB][HH];   // [layer][parity][batch][unit]
__device__ unsigned g_cnt;
__device__ unsigned g_gen;

__device__ __forceinline__ void grid_sync() {
    __syncthreads();
    if (threadIdx.x == 0) {
        __threadfence();
        unsigned gen = *(volatile unsigned*)&g_gen;
        unsigned old = atomicAdd(&g_cnt, 1u);
        if (old == NBLK - 1) {
            *(volatile unsigned*)&g_cnt = 0u;
            __threadfence();
            atomicAdd(&g_gen, 1u);
        } else {
            while (*(volatile unsigned*)&g_gen == gen) { __nanosleep(20); }
        }
        __threadfence();
    }
    __syncthreads();
}

__device__ __forceinline__ float sigf(float x) {
    return 1.0f / (1.0f + __expf(-x));
}

// One layer-phase: gates = U @ WmatA^T + V_masked @ WmatB^T + bias; LSTM cell update.
__device__ __forceinline__ void phase(
    float* __restrict__ sm,
    const int* __restrict__ mS,
    const float* __restrict__ h0l,
    const float* __restrict__ Ug,           // [32][512] global, unmasked
    const float* __restrict__ Vg,           // [32][512] global, masked by mS
    int matA, int matB, int l,
    float* __restrict__ hOut,
    float* __restrict__ outT,
    float* __restrict__ hN, float* __restrict__ cN, bool last,
    int j0, int tid, int bq, int rq, int ks)
{
    float* wS   = sm + OFF_W;
    float* redS = sm + OFF_RED;
    float* cS   = sm + OFF_C;
    float* c0S  = sm + OFF_C0;
    float* biasS= sm + OFF_BIAS;

    float acc[16];
#pragma unroll
    for (int i = 0; i < 16; i++) acc[i] = 0.0f;

    // staging coords: lanes cover consecutive k (coalesced LDG),
    // STS banks (33k + b) % 32 = (k + b) % 32 -> conflict-free
    const int sk  = tid & 127;
    const int sb0 = tid >> 7;               // 0..3

    float ru[8], rv[8];
    // prefetch chunk 0
#pragma unroll
    for (int i = 0; i < 8; i++) {
        int b = i * 4 + sb0;
        float uval = __ldcg(Ug + b * 512 + sk);
        float hv   = __ldcg(Vg + b * 512 + sk);
        ru[i] = uval;
        rv[i] = mS[b] ? h0l[sk] : hv;
    }
    // store chunk 0 -> buf0 (phase-entry barriers guarantee buffers free)
    {
        float* uS = sm + OFF_STG;
        float* vS = uS + 4224;
#pragma unroll
        for (int i = 0; i < 8; i++) {
            int b = i * 4 + sb0;
            uS[sk * 33 + b] = ru[i];
            vS[sk * 33 + b] = rv[i];
        }
    }
    // prefetch chunk 1
#pragma unroll
    for (int i = 0; i < 8; i++) {
        int b = i * 4 + sb0;
        int kg = CK + sk;
        float uval = __ldcg(Ug + b * 512 + kg);
        float hv   = __ldcg(Vg + b * 512 + kg);
        ru[i] = uval;
        rv[i] = mS[b] ? h0l[kg] : hv;
    }

    for (int c = 0; c < NCHUNK; c++) {
        __syncthreads();   // chunk c data visible; readers of buf[(c+1)&1] (chunk c-1) done
        if (c < NCHUNK - 1) {
            // store chunk c+1 into the other buffer (overlaps with compute of chunk c)
            float* uS = sm + OFF_STG + ((c + 1) & 1) * BUFSZ;
            float* vS = uS + 4224;
#pragma unroll
            for (int i = 0; i < 8; i++) {
                int b = i * 4 + sb0;
                uS[sk * 33 + b] = ru[i];
                vS[sk * 33 + b] = rv[i];
            }
            if (c < NCHUNK - 2) {
                int kg = (c + 2) * CK + sk;
                float h0v = h0l[kg];
#pragma unroll
                for (int i = 0; i < 8; i++) {
                    int b = i * 4 + sb0;
                    float uval = __ldcg(Ug + b * 512 + kg);
                    float hv   = __ldcg(Vg + b * 512 + kg);
                    ru[i] = uval;
                    rv[i] = mS[b] ? h0v : hv;
                }
            }
        }
        // compute chunk c
        const float* uS = sm + OFF_STG + (c & 1) * BUFSZ;
        const float* vS = uS + 4224;
        int kc0 = c * CK;
        int kbase = ks * KPT;
        const float* wA = wS + (matA * 512 + kc0) * 16;
        const float* wB = wS + (matB * 512 + kc0) * 16;
#pragma unroll
        for (int kk = 0; kk < KPT; kk++) {
            int k = kbase + kk;
            const float* ua = uS + k * 33 + bq * 4;
            const float* va = vS + k * 33 + bq * 4;
            float4 wa4 = *(const float4*)(wA + k * 16 + rq * 4);
            float4 wb4 = *(const float4*)(wB + k * 16 + rq * 4);
            float au[4], av[4], aw[4], bw[4];
#pragma unroll
            for (int j = 0; j < 4; j++) { au[j] = ua[j]; av[j] = va[j]; }
            aw[0] = wa4.x; aw[1] = wa4.y; aw[2] = wa4.z; aw[3] = wa4.w;
            bw[0] = wb4.x; bw[1] = wb4.y; bw[2] = wb4.z; bw[3] = wb4.w;
#pragma unroll
            for (int i = 0; i < 4; i++)
#pragma unroll
                for (int j = 0; j < 4; j++)
                    acc[i * 4 + j] += aw[i] * au[j];
#pragma unroll
            for (int i = 0; i < 4; i++)
#pragma unroll
                for (int j = 0; j < 4; j++)
                    acc[i * 4 + j] += bw[i] * av[j];
        }
    }

    // ---- cross-k-slice reduction + LSTM cell update ----
    __syncthreads();   // all compute reads of staging done (redS aliases buffers)
#pragma unroll
    for (int i = 0; i < 4; i++)
#pragma unroll
        for (int j = 0; j < 4; j++)
            redS[(((rq * 4 + i) * 32) + bq * 4 + j) * 17 + ks] = acc[i * 4 + j];
    __syncthreads();

    if (tid < 128) {
        int u = tid >> 5;
        int b = tid & 31;
        float pre[4];
#pragma unroll
        for (int g = 0; g < 4; g++) {
            float s = biasS[l * 16 + g * 4 + u];
#pragma unroll
            for (int q = 0; q < NSLICE; q++)
                s += redS[((g * 4 + u) * 32 + b) * 17 + q];
            pre[g] = s;
        }
        float cp = cS[(l * 4 + u) * 32 + b];
        if (mS[b]) cp = c0S[l * 4 + u];
        float ig = sigf(pre[0]);
        float fg = sigf(pre[1]);
        float gg = tanhf(pre[2]);
        float og = sigf(pre[3]);
        float cn = fg * cp + ig * gg;
        float hn = og * tanhf(cn);
        cS[(l * 4 + u) * 32 + b] = cn;
        __stcg(hOut + b * HH + j0 + u, hn);
        if (outT) outT[b * HH + j0 + u] = hn;
        if (last) {
            hN[(l * BB + b) * HH + j0 + u] = hn;
            cN[(l * BB + b) * HH + j0 + u] = cn;
        }
    }
}

__global__ void __launch_bounds__(NTH, 1)
lstm_kernel(const float* __restrict__ x,
            const int* __restrict__ rmask,
            const float* __restrict__ w_ih,
            const float* __restrict__ w_hh,
            const float* __restrict__ b_ih,
            const float* __restrict__ b_hh,
            const float* __restrict__ h0,
            const float* __restrict__ c0,
            float* __restrict__ out)
{
    extern __shared__ float sm[];
    float* wS    = sm + OFF_W;
    float* h0S   = sm + OFF_H0;
    float* biasS = sm + OFF_BIAS;
    float* cS    = sm + OFF_C;
    float* c0S   = sm + OFF_C0;
    int*   mS    = (int*)(sm + OFF_M);

    const int tid = threadIdx.x;
    const int bid = blockIdx.x;
    const int j0 = bid * 4;

    const int bq = tid & 7;          // batch quad
    const int rq = (tid >> 3) & 3;   // row quad (gate)
    const int ks = tid >> 5;         // k slice (warp id), 0..15

    // ---- one-time weight load: k-major, 16 rows per matrix ----
    for (int f = tid; f < 4 * 16 * 512; f += NTH) {
        int k = f & 511;
        int mr = f >> 9;
        int m = mr >> 4;
        int r = mr & 15;
        int gate = r >> 2, u = r & 3;
        int row = gate * HH + j0 + u;
        int l = m >> 1;
        const float* src;
        if ((m & 1) == 0) src = w_ih + ((size_t)l * GG + row) * II + k;
        else              src = w_hh + ((size_t)l * GG + row) * HH + k;
        wS[(m * 512 + k) * 16 + r] = __ldg(src);
    }
    if (tid < 32) {
        int l = tid >> 4;
        int r = tid & 15;
        int gate = r >> 2, u = r & 3;
        int row = gate * HH + j0 + u;
        biasS[tid] = __ldg(b_ih + l * GG + row) + __ldg(b_hh + l * GG + row);
    }
    for (int f = tid; f < 2 * HH; f += NTH) h0S[f] = __ldg(h0 + f);
    if (tid < 8) {
        int l = tid >> 2, u = tid & 3;
        c0S[tid] = __ldg(c0 + l * HH + j0 + u);
    }
    __syncthreads();
    for (int f = tid; f < 2 * 4 * 32; f += NTH) {
        int l = f >> 7;
        int u = (f >> 5) & 3;
        cS[f] = c0S[l * 4 + u];
    }
    if (tid < 256) {
        int l = tid >> 7, b = (tid >> 2) & 31, u = tid & 3;
        __stcg(&g_h[l][0][b][j0 + u], h0S[l * HH + j0 + u]);
    }
    grid_sync();

    float* hN = out + (size_t)TT * BB * HH;
    float* cN = hN + 2 * BB * HH;

    for (int t = 0; t < TT; t++) {
        int par = t & 1;
        __syncthreads();  // prior epilogue readers of mS / staging done
        if (tid < 32) mS[tid] = __ldg(rmask + t * BB + tid);
        __syncthreads();  // mS visible before phase1 prefetch/stores
        bool last = (t == TT - 1);

        // phase 1: layer 0. U = x[t], V = masked h_l0(prev)
        phase(sm, mS, h0S,
              x + (size_t)t * BB * II,
              &g_h[0][par][0][0],
              0, 1, 0,
              &g_h[0][par ^ 1][0][0],
              nullptr, hN, cN, last,
              j0, tid, bq, rq, ks);

        grid_sync();

        // phase 2: layer 1. U = fresh h_l0, V = masked h_l1(prev)
        phase(sm, mS, h0S + HH,
              &g_h[0][par ^ 1][0][0],
              &g_h[1][par][0][0],
              2, 3, 1,
              &g_h[1][par ^ 1][0][0],
              out + (size_t)t * BB * HH, hN, cN, last,
              j0, tid, bq, rq, ks);
        // (no end-of-step grid sync needed: parity double-buffering makes the
        //  only cross-block hazards pass through the mid-step sync)
    }
}

extern "C" void kernel_launch(void* const* d_in, const int* in_sizes, int n_in,
                              void* d_out, int out_size) {
    const float* x    = (const float*)d_in[0];
    const int*   rm   = (const int*)d_in[1];
    const float* w_ih = (const float*)d_in[2];
    const float* w_hh = (const float*)d_in[3];
    const float* b_ih = (const float*)d_in[4];
    const float* b_hh = (const float*)d_in[5];
    const float* h0   = (const float*)d_in[6];
    const float* c0   = (const float*)d_in[7];
    float* out = (float*)d_out;

    cudaFuncSetAttribute(lstm_kernel, cudaFuncAttributeMaxDynamicSharedMemorySize, SMEM_BYTES);
    lstm_kernel<<<NBLK, NTH, SMEM_BYTES>>>(x, rm, w_ih, w_hh, b_ih, b_hh, h0, c0, out);
}

// round 11
// speedup vs baseline: 1.9583x; 1.2729x over previous
#include <cuda_runtime.h>

#define TT 1024
#define BB 32
#define II 512
#define HH 512
#define GG 2048
#define NBLK 128
#define NTH 512
#define CK 128
#define NCHUNK 4
#define KPT 16
#define NSLICE 8
#define RPB 32           // gate rows per block (8 units * 4 gates)

// shared memory layout (float offsets)
#define OFF_W    0        // 2 mats * 512 k * 32 rows (k-major, stride 32) = 32768
#define OFF_STG  32768    // two staging buffers of 8448 (U 4224 + V 4224)
#define BUFSZ    8448
#define OFF_RED  32768    // 1024*9 = 9216, aliases staging (dead at red time)
#define OFF_H0   49664    // 512 (own layer)
#define OFF_BIAS 50176    // 32
#define OFF_C    50208    // 8 units * 32 batch = 256
#define OFF_C0   50464    // 8
#define OFF_M    50472    // 32 ints
#define SMEM_FLOATS 50504
#define SMEM_BYTES (SMEM_FLOATS * 4)

__device__ float g_h[2][2][BB][HH];   // [layer][parity][batch][unit]
__device__ unsigned g_cnt;
__device__ unsigned g_gen;

__device__ __forceinline__ void grid_sync() {
    __syncthreads();
    if (threadIdx.x == 0) {
        __threadfence();
        unsigned gen = *(volatile unsigned*)&g_gen;
        unsigned old = atomicAdd(&g_cnt, 1u);
        if (old == NBLK - 1) {
            *(volatile unsigned*)&g_cnt = 0u;
            __threadfence();
            atomicAdd(&g_gen, 1u);
        } else {
            while (*(volatile unsigned*)&g_gen == gen) { __nanosleep(20); }
        }
        __threadfence();
    }
    __syncthreads();
}

__device__ __forceinline__ float sigf(float x) {
    return 1.0f / (1.0f + __expf(-x));
}

__global__ void __launch_bounds__(NTH, 1)
lstm_kernel(const float* __restrict__ x,
            const int* __restrict__ rmask,
            const float* __restrict__ w_ih,
            const float* __restrict__ w_hh,
            const float* __restrict__ b_ih,
            const float* __restrict__ b_hh,
            const float* __restrict__ h0,
            const float* __restrict__ c0,
            float* __restrict__ out)
{
    extern __shared__ float sm[];
    float* wS    = sm + OFF_W;
    float* redS  = sm + OFF_RED;
    float* h0S   = sm + OFF_H0;
    float* biasS = sm + OFF_BIAS;
    float* cS    = sm + OFF_C;
    float* c0S   = sm + OFF_C0;
    int*   mS    = (int*)(sm + OFF_M);

    const int tid = threadIdx.x;
    const int bid = blockIdx.x;
    const int layer = bid >> 6;          // 0..1
    const int lb = bid & 63;             // block within layer group
    const int j0 = lb * 8;               // 8 units per block

    const int bq = tid & 7;              // batch quad
    const int rq = (tid >> 3) & 7;       // row quad (8 quads of 4 rows)
    const int ks = tid >> 6;             // k slice, 0..7

    // ---- one-time weight load: k-major, 32 rows per matrix (own layer) ----
    // m=0: w_ih[layer], m=1: w_hh[layer]; row r: gate = r>>3, unit = r&7
    for (int f = tid; f < 2 * RPB * 512; f += NTH) {
        int k = f & 511;
        int mr = f >> 9;                  // 0..63
        int m = mr >> 5;
        int r = mr & 31;
        int gate = r >> 3, u = r & 7;
        size_t row = (size_t)layer * GG + gate * HH + j0 + u;
        const float* src = (m == 0) ? (w_ih + row * II + k) : (w_hh + row * HH + k);
        wS[(m * 512 + k) * RPB + r] = __ldg(src);
    }
    if (tid < RPB) {
        int gate = tid >> 3, u = tid & 7;
        size_t row = (size_t)layer * GG + gate * HH + j0 + u;
        biasS[tid] = __ldg(b_ih + row) + __ldg(b_hh + row);
    }
    for (int f = tid; f < HH; f += NTH) h0S[f] = __ldg(h0 + layer * HH + f);
    if (tid < 8) c0S[tid] = __ldg(c0 + layer * HH + j0 + tid);
    __syncthreads();
    if (tid < 256) cS[tid] = c0S[tid >> 5];
    // init h state (parity 1 = "h at t=-1") for own layer's units
    if (tid < 256) {
        int b = tid >> 3, u = tid & 7;
        __stcg(&g_h[layer][1][b][j0 + u], h0S[j0 + u]);
    }
    grid_sync();

    float* hN = out + (size_t)TT * BB * HH;
    float* cN = hN + 2 * BB * HH;

    const int sk  = tid & 127;           // staging: lane covers consecutive k
    const int sb0 = tid >> 7;            // 0..3

    for (int s = 0; s <= TT; s++) {
        const int t = (layer == 0) ? s : (s - 1);
        const bool active = (layer == 0) ? (s < TT) : (s >= 1);

        if (active) {
            const int par = t & 1;
            __syncthreads();  // prior epilogue readers of mS / staging done
            if (tid < 32) mS[tid] = __ldg(rmask + t * BB + tid);
            __syncthreads();  // mS visible before prefetch

            const float* Ug = (layer == 0) ? (x + (size_t)t * BB * II)
                                           : &g_h[0][par][0][0];
            const float* Vg = &g_h[layer][par ^ 1][0][0];
            float* hOut = &g_h[layer][par][0][0];
            const bool last = (t == TT - 1);

            float acc[16];
#pragma unroll
            for (int i = 0; i < 16; i++) acc[i] = 0.0f;

            float ru[8], rv[8];
            // prefetch chunk 0
#pragma unroll
            for (int i = 0; i < 8; i++) {
                int b = i * 4 + sb0;
                float uval = __ldcg(Ug + b * 512 + sk);
                float hv   = __ldcg(Vg + b * 512 + sk);
                ru[i] = uval;
                rv[i] = mS[b] ? h0S[sk] : hv;
            }
            // store chunk 0 -> buf0
            {
                float* uS = sm + OFF_STG;
                float* vS = uS + 4224;
#pragma unroll
                for (int i = 0; i < 8; i++) {
                    int b = i * 4 + sb0;
                    uS[sk * 33 + b] = ru[i];
                    vS[sk * 33 + b] = rv[i];
                }
            }
            // prefetch chunk 1
#pragma unroll
            for (int i = 0; i < 8; i++) {
                int b = i * 4 + sb0;
                int kg = CK + sk;
                float uval = __ldcg(Ug + b * 512 + kg);
                float hv   = __ldcg(Vg + b * 512 + kg);
                ru[i] = uval;
                rv[i] = mS[b] ? h0S[kg] : hv;
            }

            for (int c = 0; c < NCHUNK; c++) {
                __syncthreads();   // chunk c visible; readers of other buf done
                if (c < NCHUNK - 1) {
                    float* uS = sm + OFF_STG + ((c + 1) & 1) * BUFSZ;
                    float* vS = uS + 4224;
#pragma unroll
                    for (int i = 0; i < 8; i++) {
                        int b = i * 4 + sb0;
                        uS[sk * 33 + b] = ru[i];
                        vS[sk * 33 + b] = rv[i];
                    }
                    if (c < NCHUNK - 2) {
                        int kg = (c + 2) * CK + sk;
                        float h0v = h0S[kg];
#pragma unroll
                        for (int i = 0; i < 8; i++) {
                            int b = i * 4 + sb0;
                            float uval = __ldcg(Ug + b * 512 + kg);
                            float hv   = __ldcg(Vg + b * 512 + kg);
                            ru[i] = uval;
                            rv[i] = mS[b] ? h0v : hv;
                        }
                    }
                }
                // compute chunk c
                const float* uS = sm + OFF_STG + (c & 1) * BUFSZ;
                const float* vS = uS + 4224;
                int kc0 = c * CK;
                int kbase = ks * KPT;
                const float* wA = wS + kc0 * RPB;            // w_ih
                const float* wB = wS + (512 + kc0) * RPB;    // w_hh
#pragma unroll
                for (int kk = 0; kk < KPT; kk++) {
                    int k = kbase + kk;
                    const float* ua = uS + k * 33 + bq * 4;
                    const float* va = vS + k * 33 + bq * 4;
                    float4 wa4 = *(const float4*)(wA + k * RPB + rq * 4);
                    float4 wb4 = *(const float4*)(wB + k * RPB + rq * 4);
                    float au[4], av[4], aw[4], bw[4];
#pragma unroll
                    for (int j = 0; j < 4; j++) { au[j] = ua[j]; av[j] = va[j]; }
                    aw[0] = wa4.x; aw[1] = wa4.y; aw[2] = wa4.z; aw[3] = wa4.w;
                    bw[0] = wb4.x; bw[1] = wb4.y; bw[2] = wb4.z; bw[3] = wb4.w;
#pragma unroll
                    for (int i = 0; i < 4; i++)
#pragma unroll
                        for (int j = 0; j < 4; j++)
                            acc[i * 4 + j] += aw[i] * au[j];
#pragma unroll
                    for (int i = 0; i < 4; i++)
#pragma unroll
                        for (int j = 0; j < 4; j++)
                            acc[i * 4 + j] += bw[i] * av[j];
                }
            }

            // ---- cross-k-slice reduction + LSTM cell update ----
            __syncthreads();   // compute reads done (redS aliases staging)
#pragma unroll
            for (int i = 0; i < 4; i++)
#pragma unroll
                for (int j = 0; j < 4; j++)
                    redS[(((rq * 4 + i) * 32) + bq * 4 + j) * 9 + ks] = acc[i * 4 + j];
            __syncthreads();

            if (tid < 256) {
                int u = tid >> 5;             // unit 0..7
                int b = tid & 31;
                float pre[4];
#pragma unroll
                for (int g = 0; g < 4; g++) {
                    float ss = biasS[g * 8 + u];
#pragma unroll
                    for (int q = 0; q < NSLICE; q++)
                        ss += redS[((g * 8 + u) * 32 + b) * 9 + q];
                    pre[g] = ss;
                }
                float cp = cS[u * 32 + b];
                if (mS[b]) cp = c0S[u];
                float ig = sigf(pre[0]);
                float fg = sigf(pre[1]);
                float gg = tanhf(pre[2]);
                float og = sigf(pre[3]);
                float cn = fg * cp + ig * gg;
                float hn = og * tanhf(cn);
                cS[u * 32 + b] = cn;
                __stcg(hOut + b * HH + j0 + u, hn);
                if (layer == 1) out[(size_t)t * BB * HH + b * HH + j0 + u] = hn;
                if (last) {
                    hN[((size_t)layer * BB + b) * HH + j0 + u] = hn;
                    cN[((size_t)layer * BB + b) * HH + j0 + u] = cn;
                }
            }
        }

        grid_sync();
    }
}

extern "C" void kernel_launch(void* const* d_in, const int* in_sizes, int n_in,
                              void* d_out, int out_size) {
    const float* x    = (const float*)d_in[0];
    const int*   rm   = (const int*)d_in[1];
    const float* w_ih = (const float*)d_in[2];
    const float* w_hh = (const float*)d_in[3];
    const float* b_ih = (const float*)d_in[4];
    const float* b_hh = (const float*)d_in[5];
    const float* h0   = (const float*)d_in[6];
    const float* c0   = (const float*)d_in[7];
    float* out = (float*)d_out;

    cudaFuncSetAttribute(lstm_kernel, cudaFuncAttributeMaxDynamicSharedMemorySize, SMEM_BYTES);
    lstm_kernel<<<NBLK, NTH, SMEM_BYTES>>>(x, rm, w_ih, w_hh, b_ih, b_hh, h0, c0, out);
}

// round 13
// speedup vs baseline: 2.0124x; 1.0276x over previous
#include <cuda_runtime.h>

#define TT 1024
#define BB 32
#define II 512
#define HH 512
#define GG 2048
#define NBLK 128
#define NTH 512
#define CK 128
#define NCHUNK 4
#define KPT 8
#define NSLICE 16
#define RPB 32           // gate rows per block (8 units * 4 gates)

// shared memory layout (float offsets)
#define OFF_W    0        // 2 mats * 512 k * 32 rows (k-major, stride 32) = 32768
#define OFF_STG  32768    // two staging buffers of 8448 (U 4224 + V 4224)
#define BUFSZ    8448
#define OFF_RED  32768    // 32 rows * 16 slices * 33 = 16896, aliases both staging buffers
#define OFF_H0   49664    // 512 (own layer)
#define OFF_BIAS 50176    // 32
#define OFF_C    50208    // 8 units * 32 batch = 256
#define OFF_C0   50464    // 8
#define OFF_M    50472    // 32 ints
#define SMEM_FLOATS 50504
#define SMEM_BYTES (SMEM_FLOATS * 4)

__device__ float g_h[2][2][BB][HH];   // [layer][parity][batch][unit]
__device__ unsigned g_cnt;
__device__ unsigned g_gen;

__device__ __forceinline__ void grid_sync() {
    __syncthreads();
    if (threadIdx.x == 0) {
        __threadfence();
        unsigned gen = *(volatile unsigned*)&g_gen;
        unsigned old = atomicAdd(&g_cnt, 1u);
        if (old == NBLK - 1) {
            *(volatile unsigned*)&g_cnt = 0u;
            __threadfence();
            atomicAdd(&g_gen, 1u);
        } else {
            while (*(volatile unsigned*)&g_gen == gen) { __nanosleep(20); }
        }
        __threadfence();
    }
    __syncthreads();
}

__device__ __forceinline__ float sigf(float x) {
    return 1.0f / (1.0f + __expf(-x));
}

__global__ void __launch_bounds__(NTH, 1)
lstm_kernel(const float* __restrict__ x,
            const int* __restrict__ rmask,
            const float* __restrict__ w_ih,
            const float* __restrict__ w_hh,
            const float* __restrict__ b_ih,
            const float* __restrict__ b_hh,
            const float* __restrict__ h0,
            const float* __restrict__ c0,
            float* __restrict__ out)
{
    extern __shared__ float sm[];
    float* wS    = sm + OFF_W;
    float* redS  = sm + OFF_RED;
    float* h0S   = sm + OFF_H0;
    float* biasS = sm + OFF_BIAS;
    float* cS    = sm + OFF_C;
    float* c0S   = sm + OFF_C0;
    int*   mS    = (int*)(sm + OFF_M);

    const int tid = threadIdx.x;
    const int bid = blockIdx.x;
    const int layer = bid >> 6;          // 0..1
    const int lb = bid & 63;             // block within layer group
    const int j0 = lb * 8;               // 8 units per block

    const int bq = tid & 7;              // batch quad (0..7)
    const int rq = (tid >> 3) & 3;       // row quad; thread owns rows rq*4+i and rq*4+16+i
    const int ks = tid >> 5;             // k slice, 0..15

    // ---- one-time weight load: k-major, 32 rows per matrix (own layer) ----
    for (int f = tid; f < 2 * RPB * 512; f += NTH) {
        int k = f & 511;
        int mr = f >> 9;                  // 0..63
        int m = mr >> 5;
        int r = mr & 31;
        int gate = r >> 3, u = r & 7;
        size_t row = (size_t)layer * GG + gate * HH + j0 + u;
        const float* src = (m == 0) ? (w_ih + row * II + k) : (w_hh + row * HH + k);
        wS[(m * 512 + k) * RPB + r] = __ldg(src);
    }
    if (tid < RPB) {
        int gate = tid >> 3, u = tid & 7;
        size_t row = (size_t)layer * GG + gate * HH + j0 + u;
        biasS[tid] = __ldg(b_ih + row) + __ldg(b_hh + row);
    }
    for (int f = tid; f < HH; f += NTH) h0S[f] = __ldg(h0 + layer * HH + f);
    if (tid < 8) c0S[tid] = __ldg(c0 + layer * HH + j0 + tid);
    __syncthreads();
    if (tid < 256) cS[tid] = c0S[tid >> 5];
    if (tid < 256) {
        int b = tid >> 3, u = tid & 7;
        __stcg(&g_h[layer][1][b][j0 + u], h0S[j0 + u]);
    }
    grid_sync();

    float* hN = out + (size_t)TT * BB * HH;
    float* cN = hN + 2 * BB * HH;

    const int sk  = tid & 127;           // staging: lane covers consecutive k
    const int sb0 = tid >> 7;            // 0..3

    for (int s = 0; s <= TT; s++) {
        const int t = (layer == 0) ? s : (s - 1);
        const bool active = (layer == 0) ? (s < TT) : (s >= 1);

        if (active) {
            const int par = t & 1;
            __syncthreads();  // prior epilogue readers of mS / redS done
            if (tid < 32) mS[tid] = __ldg(rmask + t * BB + tid);
            __syncthreads();  // mS visible before prefetch

            const float* Ug = (layer == 0) ? (x + (size_t)t * BB * II)
                                           : &g_h[0][par][0][0];
            const float* Vg = &g_h[layer][par ^ 1][0][0];
            float* hOut = &g_h[layer][par][0][0];
            const bool last = (t == TT - 1);

            float acc[32];   // [q][i][j]: q=row-half, i=row in quad, j=batch in quad
#pragma unroll
            for (int i = 0; i < 32; i++) acc[i] = 0.0f;

            float ru[8], rv[8];
            // prefetch chunk 0
#pragma unroll
            for (int i = 0; i < 8; i++) {
                int b = i * 4 + sb0;
                float uval = __ldcg(Ug + b * 512 + sk);
                float hv   = __ldcg(Vg + b * 512 + sk);
                ru[i] = uval;
                rv[i] = mS[b] ? h0S[sk] : hv;
            }
            // store chunk 0 -> buf0
            {
                float* uS = sm + OFF_STG;
                float* vS = uS + 4224;
#pragma unroll
                for (int i = 0; i < 8; i++) {
                    int b = i * 4 + sb0;
                    uS[sk * 33 + b] = ru[i];
                    vS[sk * 33 + b] = rv[i];
                }
            }
            // prefetch chunk 1
#pragma unroll
            for (int i = 0; i < 8; i++) {
                int b = i * 4 + sb0;
                int kg = CK + sk;
                float uval = __ldcg(Ug + b * 512 + kg);
                float hv   = __ldcg(Vg + b * 512 + kg);
                ru[i] = uval;
                rv[i] = mS[b] ? h0S[kg] : hv;
            }

            for (int c = 0; c < NCHUNK; c++) {
                __syncthreads();   // chunk c visible; readers of other buf done
                if (c < NCHUNK - 1) {
                    float* uS = sm + OFF_STG + ((c + 1) & 1) * BUFSZ;
                    float* vS = uS + 4224;
#pragma unroll
                    for (int i = 0; i < 8; i++) {
                        int b = i * 4 + sb0;
                        uS[sk * 33 + b] = ru[i];
                        vS[sk * 33 + b] = rv[i];
                    }
                    if (c < NCHUNK - 2) {
                        int kg = (c + 2) * CK + sk;
                        float h0v = h0S[kg];
#pragma unroll
                        for (int i = 0; i < 8; i++) {
                            int b = i * 4 + sb0;
                            float uval = __ldcg(Ug + b * 512 + kg);
                            float hv   = __ldcg(Vg + b * 512 + kg);
                            ru[i] = uval;
                            rv[i] = mS[b] ? h0v : hv;
                        }
                    }
                }
                // compute chunk c
                const float* uS = sm + OFF_STG + (c & 1) * BUFSZ;
                const float* vS = uS + 4224;
                int kbase = ks * KPT;
                const float* wA = wS + (c * CK) * RPB;            // w_ih
                const float* wB = wS + (512 + c * CK) * RPB;      // w_hh
#pragma unroll
                for (int kk = 0; kk < KPT; kk++) {
                    int k = kbase + kk;
                    const float* ua = uS + k * 33 + bq * 4;       // scalar loads (stride 33: unaligned for float4)
                    const float* va = vS + k * 33 + bq * 4;
                    const float* wAk = wA + k * RPB + rq * 4;
                    const float* wBk = wB + k * RPB + rq * 4;
                    float4 wa0 = *(const float4*)(wAk);
                    float4 wa1 = *(const float4*)(wAk + 16);
                    float4 wb0 = *(const float4*)(wBk);
                    float4 wb1 = *(const float4*)(wBk + 16);
                    float au[4], av[4];
#pragma unroll
                    for (int j = 0; j < 4; j++) { au[j] = ua[j]; av[j] = va[j]; }
                    float a0[4] = {wa0.x, wa0.y, wa0.z, wa0.w};
                    float a1[4] = {wa1.x, wa1.y, wa1.z, wa1.w};
                    float b0[4] = {wb0.x, wb0.y, wb0.z, wb0.w};
                    float b1[4] = {wb1.x, wb1.y, wb1.z, wb1.w};
#pragma unroll
                    for (int i = 0; i < 4; i++)
#pragma unroll
                        for (int j = 0; j < 4; j++) {
                            acc[i * 4 + j]      += a0[i] * au[j];
                            acc[16 + i * 4 + j] += a1[i] * au[j];
                        }
#pragma unroll
                    for (int i = 0; i < 4; i++)
#pragma unroll
                        for (int j = 0; j < 4; j++) {
                            acc[i * 4 + j]      += b0[i] * av[j];
                            acc[16 + i * 4 + j] += b1[i] * av[j];
                        }
                }
            }

            // ---- cross-k-slice reduction + LSTM cell update ----
            // redS layout: [(row*16 + slice)*33 + b] -> epilogue reads conflict-free
            __syncthreads();   // compute reads done (redS aliases staging)
#pragma unroll
            for (int q = 0; q < 2; q++)
#pragma unroll
                for (int i = 0; i < 4; i++)
#pragma unroll
                    for (int j = 0; j < 4; j++) {
                        int r = rq * 4 + i + q * 16;
                        int b = bq * 4 + j;
                        redS[(r * 16 + ks) * 33 + b] = acc[q * 16 + i * 4 + j];
                    }
            __syncthreads();

            if (tid < 256) {
                int u = tid >> 5;             // unit 0..7
                int b = tid & 31;
                float pre[4];
#pragma unroll
                for (int g = 0; g < 4; g++) {
                    int r = g * 8 + u;
                    const float* base = redS + r * 16 * 33 + b;
                    float s0 = biasS[r];
                    float s1 = 0.0f, s2 = 0.0f, s3 = 0.0f;
#pragma unroll
                    for (int q = 0; q < NSLICE; q += 4) {
                        s0 += base[(q + 0) * 33];
                        s1 += base[(q + 1) * 33];
                        s2 += base[(q + 2) * 33];
                        s3 += base[(q + 3) * 33];
                    }
                    pre[g] = (s0 + s1) + (s2 + s3);
                }
                float cp = cS[u * 32 + b];
                if (mS[b]) cp = c0S[u];
                float ig = sigf(pre[0]);
                float fg = sigf(pre[1]);
                float gg = tanhf(pre[2]);
                float og = sigf(pre[3]);
                float cn = fg * cp + ig * gg;
                float hn = og * tanhf(cn);
                cS[u * 32 + b] = cn;
                __stcg(hOut + b * HH + j0 + u, hn);
                if (layer == 1) out[(size_t)t * BB * HH + b * HH + j0 + u] = hn;
                if (last) {
                    hN[((size_t)layer * BB + b) * HH + j0 + u] = hn;
                    cN[((size_t)layer * BB + b) * HH + j0 + u] = cn;
                }
            }
        }

        grid_sync();
    }
}

extern "C" void kernel_launch(void* const* d_in, const int* in_sizes, int n_in,
                              void* d_out, int out_size) {
    const float* x    = (const float*)d_in[0];
    const int*   rm   = (const int*)d_in[1];
    const float* w_ih = (const float*)d_in[2];
    const float* w_hh = (const float*)d_in[3];
    const float* b_ih = (const float*)d_in[4];
    const float* b_hh = (const float*)d_in[5];
    const float* h0   = (const float*)d_in[6];
    const float* c0   = (const float*)d_in[7];
    float* out = (float*)d_out;

    cudaFuncSetAttribute(lstm_kernel, cudaFuncAttributeMaxDynamicSharedMemorySize, SMEM_BYTES);
    lstm_kernel<<<NBLK, NTH, SMEM_BYTES>>>(x, rm, w_ih, w_hh, b_ih, b_hh, h0, c0, out);
}

// round 14
// speedup vs baseline: 2.0312x; 1.0094x over previous
#include <cuda_runtime.h>

#define TT 1024
#define BB 32
#define II 512
#define HH 512
#define GG 2048
#define NBLK 128
#define NTH 512
#define CK 128
#define NCHUNK 4
#define KPT 8
#define NSLICE 16
#define RPB 32           // gate rows per block (8 units * 4 gates)

// shared memory layout (float offsets)
#define OFF_W    0        // 2 mats * 512 k * 32 rows (k-major, stride 32) = 32768
#define OFF_STG  32768    // two staging buffers of 8448 (U 4224 + V 4224)
#define BUFSZ    8448
#define OFF_RED  32768    // 32 rows * 16 slices * 33 = 16896, aliases both staging buffers
#define OFF_H0   49664    // 512 (own layer)
#define OFF_BIAS 50176    // 32
#define OFF_C    50208    // 8 units * 32 batch = 256
#define OFF_C0   50464    // 8
#define OFF_M    50472    // 32 ints
#define SMEM_FLOATS 50504
#define SMEM_BYTES (SMEM_FLOATS * 4)

__device__ float g_h[2][2][BB][HH];   // [layer][parity][batch][unit]
__device__ unsigned g_cnt;
__device__ unsigned g_gen;

__device__ __forceinline__ void grid_sync() {
    __syncthreads();
    if (threadIdx.x == 0) {
        __threadfence();
        unsigned gen = *(volatile unsigned*)&g_gen;
        unsigned old = atomicAdd(&g_cnt, 1u);
        if (old == NBLK - 1) {
            *(volatile unsigned*)&g_cnt = 0u;
            __threadfence();
            atomicAdd(&g_gen, 1u);
        } else {
            while (*(volatile unsigned*)&g_gen == gen) { __nanosleep(20); }
        }
        __threadfence();
    }
    __syncthreads();
}

__device__ __forceinline__ float sigf(float x) {
    return 1.0f / (1.0f + __expf(-x));
}

__global__ void __launch_bounds__(NTH, 1)
lstm_kernel(const float* __restrict__ x,
            const int* __restrict__ rmask,
            const float* __restrict__ w_ih,
            const float* __restrict__ w_hh,
            const float* __restrict__ b_ih,
            const float* __restrict__ b_hh,
            const float* __restrict__ h0,
            const float* __restrict__ c0,
            float* __restrict__ out)
{
    extern __shared__ float sm[];
    float* wS    = sm + OFF_W;
    float* redS  = sm + OFF_RED;
    float* h0S   = sm + OFF_H0;
    float* biasS = sm + OFF_BIAS;
    float* cS    = sm + OFF_C;
    float* c0S   = sm + OFF_C0;
    int*   mS    = (int*)(sm + OFF_M);

    const int tid = threadIdx.x;
    const int bid = blockIdx.x;
    const int layer = bid >> 6;          // 0..1
    const int lb = bid & 63;             // block within layer group
    const int j0 = lb * 8;               // 8 units per block

    const int bq = tid & 7;              // batch quad (0..7)
    const int rq = (tid >> 3) & 3;       // row quad; thread owns rows rq*4+i and rq*4+16+i
    const int ks = tid >> 5;             // k slice, 0..15

    // ---- one-time weight load: k-major, 32 rows per matrix (own layer) ----
    for (int f = tid; f < 2 * RPB * 512; f += NTH) {
        int k = f & 511;
        int mr = f >> 9;                  // 0..63
        int m = mr >> 5;
        int r = mr & 31;
        int gate = r >> 3, u = r & 7;
        size_t row = (size_t)layer * GG + gate * HH + j0 + u;
        const float* src = (m == 0) ? (w_ih + row * II + k) : (w_hh + row * HH + k);
        wS[(m * 512 + k) * RPB + r] = __ldg(src);
    }
    if (tid < RPB) {
        int gate = tid >> 3, u = tid & 7;
        size_t row = (size_t)layer * GG + gate * HH + j0 + u;
        biasS[tid] = __ldg(b_ih + row) + __ldg(b_hh + row);
    }
    for (int f = tid; f < HH; f += NTH) h0S[f] = __ldg(h0 + layer * HH + f);
    if (tid < 8) c0S[tid] = __ldg(c0 + layer * HH + j0 + tid);
    __syncthreads();
    if (tid < 256) cS[tid] = c0S[tid >> 5];
    if (tid < 256) {
        int b = tid >> 3, u = tid & 7;
        __stcg(&g_h[layer][1][b][j0 + u], h0S[j0 + u]);
    }
    grid_sync();

    float* hN = out + (size_t)TT * BB * HH;
    float* cN = hN + 2 * BB * HH;

    const int sk  = tid & 127;           // staging: lane covers consecutive k
    const int sb0 = tid >> 7;            // 0..3

    for (int s = 0; s <= TT; s++) {
        const int t = (layer == 0) ? s : (s - 1);
        const bool active = (layer == 0) ? (s < TT) : (s >= 1);

        if (active) {
            const int par = t & 1;
            __syncthreads();  // prior epilogue readers of mS / redS done
            if (tid < 32) mS[tid] = __ldg(rmask + t * BB + tid);
            __syncthreads();  // mS visible before prefetch

            const float* Ug = (layer == 0) ? (x + (size_t)t * BB * II)
                                           : &g_h[0][par][0][0];
            const float* Vg = &g_h[layer][par ^ 1][0][0];
            float* hOut = &g_h[layer][par][0][0];
            const bool last = (t == TT - 1);

            float acc[32];   // [q][i][j]: q=row-half, i=row in quad, j=batch in quad
#pragma unroll
            for (int i = 0; i < 32; i++) acc[i] = 0.0f;

            float ru[8], rv[8];
            // prefetch chunk 0
#pragma unroll
            for (int i = 0; i < 8; i++) {
                int b = i * 4 + sb0;
                float uval = __ldcg(Ug + b * 512 + sk);
                float hv   = __ldcg(Vg + b * 512 + sk);
                ru[i] = uval;
                rv[i] = mS[b] ? h0S[sk] : hv;
            }
            // store chunk 0 -> buf0
            {
                float* uS = sm + OFF_STG;
                float* vS = uS + 4224;
#pragma unroll
                for (int i = 0; i < 8; i++) {
                    int b = i * 4 + sb0;
                    uS[sk * 33 + b] = ru[i];
                    vS[sk * 33 + b] = rv[i];
                }
            }
            // prefetch chunk 1
#pragma unroll
            for (int i = 0; i < 8; i++) {
                int b = i * 4 + sb0;
                int kg = CK + sk;
                float uval = __ldcg(Ug + b * 512 + kg);
                float hv   = __ldcg(Vg + b * 512 + kg);
                ru[i] = uval;
                rv[i] = mS[b] ? h0S[kg] : hv;
            }

            for (int c = 0; c < NCHUNK; c++) {
                __syncthreads();   // chunk c visible; readers of other buf done
                if (c < NCHUNK - 1) {
                    float* uS = sm + OFF_STG + ((c + 1) & 1) * BUFSZ;
                    float* vS = uS + 4224;
#pragma unroll
                    for (int i = 0; i < 8; i++) {
                        int b = i * 4 + sb0;
                        uS[sk * 33 + b] = ru[i];
                        vS[sk * 33 + b] = rv[i];
                    }
                    if (c < NCHUNK - 2) {
                        int kg = (c + 2) * CK + sk;
                        float h0v = h0S[kg];
#pragma unroll
                        for (int i = 0; i < 8; i++) {
                            int b = i * 4 + sb0;
                            float uval = __ldcg(Ug + b * 512 + kg);
                            float hv   = __ldcg(Vg + b * 512 + kg);
                            ru[i] = uval;
                            rv[i] = mS[b] ? h0v : hv;
                        }
                    }
                }
                // compute chunk c
                const float* uS = sm + OFF_STG + (c & 1) * BUFSZ;
                const float* vS = uS + 4224;
                int kbase = ks * KPT;
                const float* wA = wS + (c * CK) * RPB;            // w_ih
                const float* wB = wS + (512 + c * CK) * RPB;      // w_hh
#pragma unroll
                for (int kk = 0; kk < KPT; kk++) {
                    int k = kbase + kk;
                    const float* ua = uS + k * 33 + bq * 4;       // scalar loads (stride 33: unaligned for float4)
                    const float* va = vS + k * 33 + bq * 4;
                    const float* wAk = wA + k * RPB + rq * 4;
                    const float* wBk = wB + k * RPB + rq * 4;
                    float4 wa0 = *(const float4*)(wAk);
                    float4 wa1 = *(const float4*)(wAk + 16);
                    float4 wb0 = *(const float4*)(wBk);
                    float4 wb1 = *(const float4*)(wBk + 16);
                    float au[4], av[4];
#pragma unroll
                    for (int j = 0; j < 4; j++) { au[j] = ua[j]; av[j] = va[j]; }
                    float a0[4] = {wa0.x, wa0.y, wa0.z, wa0.w};
                    float a1[4] = {wa1.x, wa1.y, wa1.z, wa1.w};
                    float b0[4] = {wb0.x, wb0.y, wb0.z, wb0.w};
                    float b1[4] = {wb1.x, wb1.y, wb1.z, wb1.w};
#pragma unroll
                    for (int i = 0; i < 4; i++)
#pragma unroll
                        for (int j = 0; j < 4; j++) {
                            acc[i * 4 + j]      += a0[i] * au[j];
                            acc[16 + i * 4 + j] += a1[i] * au[j];
                        }
#pragma unroll
                    for (int i = 0; i < 4; i++)
#pragma unroll
                        for (int j = 0; j < 4; j++) {
                            acc[i * 4 + j]      += b0[i] * av[j];
                            acc[16 + i * 4 + j] += b1[i] * av[j];
                        }
                }
            }

            // ---- cross-k-slice reduction + LSTM cell update ----
            // redS layout: [(row*16 + slice)*33 + b] -> epilogue reads conflict-free
            __syncthreads();   // compute reads done (redS aliases staging)
#pragma unroll
            for (int q = 0; q < 2; q++)
#pragma unroll
                for (int i = 0; i < 4; i++)
#pragma unroll
                    for (int j = 0; j < 4; j++) {
                        int r = rq * 4 + i + q * 16;
                        int b = bq * 4 + j;
                        redS[(r * 16 + ks) * 33 + b] = acc[q * 16 + i * 4 + j];
                    }
            __syncthreads();

            if (tid < 256) {
                int u = tid >> 5;             // unit 0..7
                int b = tid & 31;
                float pre[4];
#pragma unroll
                for (int g = 0; g < 4; g++) {
                    int r = g * 8 + u;
                    const float* base = redS + r * 16 * 33 + b;
                    float s0 = biasS[r];
                    float s1 = 0.0f, s2 = 0.0f, s3 = 0.0f;
#pragma unroll
                    for (int q = 0; q < NSLICE; q += 4) {
                        s0 += base[(q + 0) * 33];
                        s1 += base[(q + 1) * 33];
                        s2 += base[(q + 2) * 33];
                        s3 += base[(q + 3) * 33];
                    }
                    pre[g] = (s0 + s1) + (s2 + s3);
                }
                float cp = cS[u * 32 + b];
                if (mS[b]) cp = c0S[u];
                float ig = sigf(pre[0]);
                float fg = sigf(pre[1]);
                float gg = tanhf(pre[2]);
                float og = sigf(pre[3]);
                float cn = fg * cp + ig * gg;
                float hn = og * tanhf(cn);
                cS[u * 32 + b] = cn;
                __stcg(hOut + b * HH + j0 + u, hn);
                if (layer == 1) out[(size_t)t * BB * HH + b * HH + j0 + u] = hn;
                if (last) {
                    hN[((size_t)layer * BB + b) * HH + j0 + u] = hn;
                    cN[((size_t)layer * BB + b) * HH + j0 + u] = cn;
                }
            }
        }

        grid_sync();
    }
}

extern "C" void kernel_launch(void* const* d_in, const int* in_sizes, int n_in,
                              void* d_out, int out_size) {
    const float* x    = (const float*)d_in[0];
    const int*   rm   = (const int*)d_in[1];
    const float* w_ih = (const float*)d_in[2];
    const float* w_hh = (const float*)d_in[3];
    const float* b_ih = (const float*)d_in[4];
    const float* b_hh = (const float*)d_in[5];
    const float* h0   = (const float*)d_in[6];
    const float* c0   = (const float*)d_in[7];
    float* out = (float*)d_out;

    cudaFuncSetAttribute(lstm_kernel, cudaFuncAttributeMaxDynamicSharedMemorySize, SMEM_BYTES);
    lstm_kernel<<<NBLK, NTH, SMEM_BYTES>>>(x, rm, w_ih, w_hh, b_ih, b_hh, h0, c0, out);
}

// round 15
// speedup vs baseline: 2.0420x; 1.0053x over previous
#include <cuda_runtime.h>

#define TT 1024
#define BB 32
#define II 512
#define HH 512
#define GG 2048
#define NBLK 128
#define NTH 512
#define CK 128
#define NCHUNK 4
#define KPT 8
#define NSLICE 16
#define RPB 32           // gate rows per block (8 units * 4 gates)

// shared memory layout (float offsets)
#define OFF_W    0        // 2 mats * 512 k * 32 rows (k-major, stride 32) = 32768
#define OFF_STG  32768    // two staging buffers of 8448 (U 4224 + V 4224)
#define BUFSZ    8448
#define OFF_RED  32768    // 32 rows * 16 slices * 33 = 16896, aliases both staging buffers
#define OFF_H0   49664    // 512 (own layer)
#define OFF_BIAS 50176    // 32
#define OFF_C    50208    // 8 units * 32 batch = 256
#define OFF_C0   50464    // 8
#define OFF_M    50472    // 32 ints
#define SMEM_FLOATS 50504
#define SMEM_BYTES (SMEM_FLOATS * 4)

__device__ float g_h[2][2][BB][HH];   // [layer][parity][batch][unit]
__device__ unsigned g_cnt;
__device__ unsigned g_gen;

__device__ __forceinline__ void grid_sync() {
    __syncthreads();
    if (threadIdx.x == 0) {
        __threadfence();
        unsigned gen = *(volatile unsigned*)&g_gen;
        unsigned old = atomicAdd(&g_cnt, 1u);
        if (old == NBLK - 1) {
            *(volatile unsigned*)&g_cnt = 0u;
            __threadfence();
            atomicAdd(&g_gen, 1u);
        } else {
            while (*(volatile unsigned*)&g_gen == gen) { __nanosleep(20); }
        }
        __threadfence();
    }
    __syncthreads();
}

__device__ __forceinline__ float sigf(float x) {
    return 1.0f / (1.0f + __expf(-x));
}

__global__ void __launch_bounds__(NTH, 1)
lstm_kernel(const float* __restrict__ x,
            const int* __restrict__ rmask,
            const float* __restrict__ w_ih,
            const float* __restrict__ w_hh,
            const float* __restrict__ b_ih,
            const float* __restrict__ b_hh,
            const float* __restrict__ h0,
            const float* __restrict__ c0,
            float* __restrict__ out)
{
    extern __shared__ float sm[];
    float* wS    = sm + OFF_W;
    float* redS  = sm + OFF_RED;
    float* h0S   = sm + OFF_H0;
    float* biasS = sm + OFF_BIAS;
    float* cS    = sm + OFF_C;
    float* c0S   = sm + OFF_C0;
    int*   mS    = (int*)(sm + OFF_M);

    const int tid = threadIdx.x;
    const int bid = blockIdx.x;
    const int layer = bid >> 6;          // 0..1
    const int lb = bid & 63;             // block within layer group
    const int j0 = lb * 8;               // 8 units per block

    const int bq = tid & 7;              // batch quad (0..7)
    const int rq = (tid >> 3) & 3;       // row quad; thread owns rows rq*4+i and rq*4+16+i
    const int ks = tid >> 5;             // k slice, 0..15

    // ---- one-time weight load: k-major, 32 rows per matrix (own layer) ----
    for (int f = tid; f < 2 * RPB * 512; f += NTH) {
        int k = f & 511;
        int mr = f >> 9;                  // 0..63
        int m = mr >> 5;
        int r = mr & 31;
        int gate = r >> 3, u = r & 7;
        size_t row = (size_t)layer * GG + gate * HH + j0 + u;
        const float* src = (m == 0) ? (w_ih + row * II + k) : (w_hh + row * HH + k);
        wS[(m * 512 + k) * RPB + r] = __ldg(src);
    }
    if (tid < RPB) {
        int gate = tid >> 3, u = tid & 7;
        size_t row = (size_t)layer * GG + gate * HH + j0 + u;
        biasS[tid] = __ldg(b_ih + row) + __ldg(b_hh + row);
    }
    for (int f = tid; f < HH; f += NTH) h0S[f] = __ldg(h0 + layer * HH + f);
    if (tid < 8) c0S[tid] = __ldg(c0 + layer * HH + j0 + tid);
    __syncthreads();
    if (tid < 256) cS[tid] = c0S[tid >> 5];
    if (tid < 256) {
        int b = tid >> 3, u = tid & 7;
        __stcg(&g_h[layer][1][b][j0 + u], h0S[j0 + u]);
    }
    grid_sync();

    float* hN = out + (size_t)TT * BB * HH;
    float* cN = hN + 2 * BB * HH;

    const int sk  = tid & 127;           // staging: lane covers consecutive k
    const int sb0 = tid >> 7;            // 0..3

    for (int s = 0; s <= TT; s++) {
        const int t = (layer == 0) ? s : (s - 1);
        const bool active = (layer == 0) ? (s < TT) : (s >= 1);

        if (active) {
            const int par = t & 1;
            __syncthreads();  // prior epilogue readers of mS / redS done
            if (tid < 32) mS[tid] = __ldg(rmask + t * BB + tid);
            __syncthreads();  // mS visible before prefetch

            const float* Ug = (layer == 0) ? (x + (size_t)t * BB * II)
                                           : &g_h[0][par][0][0];
            const float* Vg = &g_h[layer][par ^ 1][0][0];
            float* hOut = &g_h[layer][par][0][0];
            const bool last = (t == TT - 1);

            float acc[32];   // [q][i][j]: q=row-half, i=row in quad, j=batch in quad
#pragma unroll
            for (int i = 0; i < 32; i++) acc[i] = 0.0f;

            float ru[8], rv[8];
            // prefetch chunk 0
#pragma unroll
            for (int i = 0; i < 8; i++) {
                int b = i * 4 + sb0;
                float uval = __ldcg(Ug + b * 512 + sk);
                float hv   = __ldcg(Vg + b * 512 + sk);
                ru[i] = uval;
                rv[i] = mS[b] ? h0S[sk] : hv;
            }
            // store chunk 0 -> buf0
            {
                float* uS = sm + OFF_STG;
                float* vS = uS + 4224;
#pragma unroll
                for (int i = 0; i < 8; i++) {
                    int b = i * 4 + sb0;
                    uS[sk * 33 + b] = ru[i];
                    vS[sk * 33 + b] = rv[i];
                }
            }
            // prefetch chunk 1
#pragma unroll
            for (int i = 0; i < 8; i++) {
                int b = i * 4 + sb0;
                int kg = CK + sk;
                float uval = __ldcg(Ug + b * 512 + kg);
                float hv   = __ldcg(Vg + b * 512 + kg);
                ru[i] = uval;
                rv[i] = mS[b] ? h0S[kg] : hv;
            }

            for (int c = 0; c < NCHUNK; c++) {
                __syncthreads();   // chunk c visible; readers of other buf done
                if (c < NCHUNK - 1) {
                    float* uS = sm + OFF_STG + ((c + 1) & 1) * BUFSZ;
                    float* vS = uS + 4224;
#pragma unroll
                    for (int i = 0; i < 8; i++) {
                        int b = i * 4 + sb0;
                        uS[sk * 33 + b] = ru[i];
                        vS[sk * 33 + b] = rv[i];
                    }
                    if (c < NCHUNK - 2) {
                        int kg = (c + 2) * CK + sk;
                        float h0v = h0S[kg];
#pragma unroll
                        for (int i = 0; i < 8; i++) {
                            int b = i * 4 + sb0;
                            float uval = __ldcg(Ug + b * 512 + kg);
                            float hv   = __ldcg(Vg + b * 512 + kg);
                            ru[i] = uval;
                            rv[i] = mS[b] ? h0v : hv;
                        }
                    }
                }
                // compute chunk c
                const float* uS = sm + OFF_STG + (c & 1) * BUFSZ;
                const float* vS = uS + 4224;
                int kbase = ks * KPT;
                const float* wA = wS + (c * CK) * RPB;            // w_ih
                const float* wB = wS + (512 + c * CK) * RPB;      // w_hh
#pragma unroll
                for (int kk = 0; kk < KPT; kk++) {
                    int k = kbase + kk;
                    const float* ua = uS + k * 33 + bq * 4;       // scalar loads (stride 33: unaligned for float4)
                    const float* va = vS + k * 33 + bq * 4;
                    const float* wAk = wA + k * RPB + rq * 4;
                    const float* wBk = wB + k * RPB + rq * 4;
                    float4 wa0 = *(const float4*)(wAk);
                    float4 wa1 = *(const float4*)(wAk + 16);
                    float4 wb0 = *(const float4*)(wBk);
                    float4 wb1 = *(const float4*)(wBk + 16);
                    float au[4], av[4];
#pragma unroll
                    for (int j = 0; j < 4; j++) { au[j] = ua[j]; av[j] = va[j]; }
                    float a0[4] = {wa0.x, wa0.y, wa0.z, wa0.w};
                    float a1[4] = {wa1.x, wa1.y, wa1.z, wa1.w};
                    float b0[4] = {wb0.x, wb0.y, wb0.z, wb0.w};
                    float b1[4] = {wb1.x, wb1.y, wb1.z, wb1.w};
#pragma unroll
                    for (int i = 0; i < 4; i++)
#pragma unroll
                        for (int j = 0; j < 4; j++) {
                            acc[i * 4 + j]      += a0[i] * au[j];
                            acc[16 + i * 4 + j] += a1[i] * au[j];
                        }
#pragma unroll
                    for (int i = 0; i < 4; i++)
#pragma unroll
                        for (int j = 0; j < 4; j++) {
                            acc[i * 4 + j]      += b0[i] * av[j];
                            acc[16 + i * 4 + j] += b1[i] * av[j];
                        }
                }
            }

            // ---- cross-k-slice reduction + LSTM cell update ----
            // redS layout: [(row*16 + slice)*33 + b] -> epilogue reads conflict-free
            __syncthreads();   // compute reads done (redS aliases staging)
#pragma unroll
            for (int q = 0; q < 2; q++)
#pragma unroll
                for (int i = 0; i < 4; i++)
#pragma unroll
                    for (int j = 0; j < 4; j++) {
                        int r = rq * 4 + i + q * 16;
                        int b = bq * 4 + j;
                        redS[(r * 16 + ks) * 33 + b] = acc[q * 16 + i * 4 + j];
                    }
            __syncthreads();

            if (tid < 256) {
                int u = tid >> 5;             // unit 0..7
                int b = tid & 31;
                float pre[4];
#pragma unroll
                for (int g = 0; g < 4; g++) {
                    int r = g * 8 + u;
                    const float* base = redS + r * 16 * 33 + b;
                    float s0 = biasS[r];
                    float s1 = 0.0f, s2 = 0.0f, s3 = 0.0f;
#pragma unroll
                    for (int q = 0; q < NSLICE; q += 4) {
                        s0 += base[(q + 0) * 33];
                        s1 += base[(q + 1) * 33];
                        s2 += base[(q + 2) * 33];
                        s3 += base[(q + 3) * 33];
                    }
                    pre[g] = (s0 + s1) + (s2 + s3);
                }
                float cp = cS[u * 32 + b];
                if (mS[b]) cp = c0S[u];
                float ig = sigf(pre[0]);
                float fg = sigf(pre[1]);
                float gg = tanhf(pre[2]);
                float og = sigf(pre[3]);
                float cn = fg * cp + ig * gg;
                float hn = og * tanhf(cn);
                cS[u * 32 + b] = cn;
                __stcg(hOut + b * HH + j0 + u, hn);
                if (layer == 1) out[(size_t)t * BB * HH + b * HH + j0 + u] = hn;
                if (last) {
                    hN[((size_t)layer * BB + b) * HH + j0 + u] = hn;
                    cN[((size_t)layer * BB + b) * HH + j0 + u] = cn;
                }
            }
        }

        grid_sync();
    }
}

extern "C" void kernel_launch(void* const* d_in, const int* in_sizes, int n_in,
                              void* d_out, int out_size) {
    const float* x    = (const float*)d_in[0];
    const int*   rm   = (const int*)d_in[1];
    const float* w_ih = (const float*)d_in[2];
    const float* w_hh = (const float*)d_in[3];
    const float* b_ih = (const float*)d_in[4];
    const float* b_hh = (const float*)d_in[5];
    const float* h0   = (const float*)d_in[6];
    const float* c0   = (const float*)d_in[7];
    float* out = (float*)d_out;

    cudaFuncSetAttribute(lstm_kernel, cudaFuncAttributeMaxDynamicSharedMemorySize, SMEM_BYTES);
    lstm_kernel<<<NBLK, NTH, SMEM_BYTES>>>(x, rm, w_ih, w_hh, b_ih, b_hh, h0, c0, out);
}